// round 1
// baseline (speedup 1.0000x reference)
#include <cuda_runtime.h>
#include <math.h>
#include <stdint.h>

// Problem constants
#define NT 2048   // query tokens
#define DD 1024   // feature dim
#define CC 768    // context dim
#define NH 16     // heads
#define HD 64     // head dim
#define MT 2048   // context tokens
#define FF 4096   // MLP hidden

// ---------------- scratch (static device memory; no runtime alloc) ----------
__device__ float g_xq[NT * DD];
__device__ float g_kv[MT * CC];
__device__ float g_q[NT * DD];
__device__ float g_k[MT * DD];
__device__ float g_v[MT * DD];
__device__ float g_s[(size_t)NH * NT * MT];   // 256 MB attention scores
__device__ float g_o[NT * DD];
__device__ float g_x1[NT * DD];
__device__ float g_hln[NT * DD];
__device__ float g_h1[(size_t)NT * FF];

// ---------------- block reductions (256 threads) ----------------------------
__device__ __forceinline__ float block_reduce_sum(float v) {
    __shared__ float sh[8];
    int tid = threadIdx.x;
#pragma unroll
    for (int o = 16; o > 0; o >>= 1) v += __shfl_down_sync(0xffffffffu, v, o);
    if ((tid & 31) == 0) sh[tid >> 5] = v;
    __syncthreads();
    if (tid < 32) {
        v = (tid < 8) ? sh[tid] : 0.f;
#pragma unroll
        for (int o = 4; o > 0; o >>= 1) v += __shfl_down_sync(0xffffffffu, v, o);
        if (tid == 0) sh[0] = v;
    }
    __syncthreads();
    float r = sh[0];
    __syncthreads();
    return r;
}

__device__ __forceinline__ float block_reduce_max(float v) {
    __shared__ float sh[8];
    int tid = threadIdx.x;
#pragma unroll
    for (int o = 16; o > 0; o >>= 1) v = fmaxf(v, __shfl_down_sync(0xffffffffu, v, o));
    if ((tid & 31) == 0) sh[tid >> 5] = v;
    __syncthreads();
    if (tid < 32) {
        v = (tid < 8) ? sh[tid] : -INFINITY;
#pragma unroll
        for (int o = 4; o > 0; o >>= 1) v = fmaxf(v, __shfl_down_sync(0xffffffffu, v, o));
        if (tid == 0) sh[0] = v;
    }
    __syncthreads();
    float r = sh[0];
    __syncthreads();
    return r;
}

// ---------------- layernorm --------------------------------------------------
template <int DIM>
__global__ __launch_bounds__(256) void layernorm_kernel(
    const float* __restrict__ x, const float* __restrict__ w,
    const float* __restrict__ b, float* __restrict__ o) {
    const float* xr = x + (size_t)blockIdx.x * DIM;
    float* orow = o + (size_t)blockIdx.x * DIM;
    float s = 0.f;
    for (int i = threadIdx.x; i < DIM; i += 256) s += xr[i];
    float mean = block_reduce_sum(s) * (1.f / DIM);
    float vv = 0.f;
    for (int i = threadIdx.x; i < DIM; i += 256) {
        float c = xr[i] - mean;
        vv += c * c;
    }
    float var = block_reduce_sum(vv) * (1.f / DIM);
    float inv = rsqrtf(var + 1e-12f);
    for (int i = threadIdx.x; i < DIM; i += 256)
        orow[i] = (xr[i] - mean) * inv * w[i] + b[i];
}

// ---------------- tiled fp32 GEMM -------------------------------------------
// C[y*128.., x*64..] = alpha * A@B (+bias)(+res)(gelu), batched over blockIdx.z
// TRANS_B=1 computes A @ B^T (B stored row-major [Ncols x K], stride ldb).
#define BM 128
#define BN 64
#define BK 16

template <int HAS_BIAS, int HAS_RES, int DO_GELU, int TRANS_B>
__global__ __launch_bounds__(256) void gemm_kernel(
    const float* __restrict__ A, const float* __restrict__ B,
    const float* __restrict__ bias, const float* __restrict__ Res,
    float* __restrict__ C, int K, int lda, int ldb, int ldc,
    long long sA, long long sB, long long sC, float alpha) {
    __shared__ __align__(16) float As[BK][BM];
    __shared__ __align__(16) float Bs[BK][BN];
    const int tid = threadIdx.x;
    const int ty = tid >> 4;  // 0..15 -> rows ty*8..+7
    const int tx = tid & 15;  // 0..15 -> cols tx*4..+3

    A += (size_t)blockIdx.z * sA + (size_t)blockIdx.y * BM * lda;
    if (TRANS_B)
        B += (size_t)blockIdx.z * sB + (size_t)blockIdx.x * BN * ldb;
    else
        B += (size_t)blockIdx.z * sB + (size_t)blockIdx.x * BN;
    const size_t c_off =
        (size_t)blockIdx.z * sC + (size_t)blockIdx.y * BM * ldc + (size_t)blockIdx.x * BN;

    float acc[8][4] = {};

    for (int k0 = 0; k0 < K; k0 += BK) {
        // A tile: 128x16 = 512 float4, 2 per thread, stored transposed [k][m]
#pragma unroll
        for (int i = 0; i < 2; i++) {
            int v = tid + i * 256;
            int r = v >> 2, kc = (v & 3) << 2;
            const float4 a = *(const float4*)(A + (size_t)r * lda + (k0 + kc));
            As[kc + 0][r] = a.x; As[kc + 1][r] = a.y;
            As[kc + 2][r] = a.z; As[kc + 3][r] = a.w;
        }
        if (TRANS_B) {
            int c = tid >> 2, kc = (tid & 3) << 2;
            const float4 bv = *(const float4*)(B + (size_t)c * ldb + (k0 + kc));
            Bs[kc + 0][c] = bv.x; Bs[kc + 1][c] = bv.y;
            Bs[kc + 2][c] = bv.z; Bs[kc + 3][c] = bv.w;
        } else {
            int kr = tid >> 4, c = (tid & 15) << 2;
            const float4 bv = *(const float4*)(B + (size_t)(k0 + kr) * ldb + c);
            *(float4*)&Bs[kr][c] = bv;
        }
        __syncthreads();
#pragma unroll
        for (int k = 0; k < BK; k++) {
            float a[8], bb[4];
#pragma unroll
            for (int i = 0; i < 8; i++) a[i] = As[k][ty * 8 + i];
#pragma unroll
            for (int j = 0; j < 4; j++) bb[j] = Bs[k][tx * 4 + j];
#pragma unroll
            for (int i = 0; i < 8; i++)
#pragma unroll
                for (int j = 0; j < 4; j++) acc[i][j] = fmaf(a[i], bb[j], acc[i][j]);
        }
        __syncthreads();
    }

#pragma unroll
    for (int i = 0; i < 8; i++) {
        int row = ty * 8 + i;
        float4 outv;
        float* po = (float*)&outv;
#pragma unroll
        for (int j = 0; j < 4; j++) {
            float v = acc[i][j] * alpha;
            if (HAS_BIAS) v += bias[(size_t)blockIdx.x * BN + tx * 4 + j];
            if (HAS_RES) v += Res[c_off + (size_t)row * ldc + tx * 4 + j];
            if (DO_GELU) {
                // JAX default gelu (approximate=True, tanh form)
                float t = v;
                float inner = 0.7978845608028654f * (t + 0.044715f * t * t * t);
                v = 0.5f * t * (1.f + tanhf(inner));
            }
            po[j] = v;
        }
        *(float4*)(C + c_off + (size_t)row * ldc + tx * 4) = outv;
    }
}

// ---------------- softmax over rows of length MT ----------------------------
__global__ __launch_bounds__(256) void softmax_kernel(float* __restrict__ S) {
    float* r = S + (size_t)blockIdx.x * MT;
    int tid = threadIdx.x;
    float vals[8];
    float vmax = -INFINITY;
#pragma unroll
    for (int i = 0; i < 8; i++) {
        vals[i] = r[tid + i * 256];
        vmax = fmaxf(vmax, vals[i]);
    }
    vmax = block_reduce_max(vmax);
    float sum = 0.f;
#pragma unroll
    for (int i = 0; i < 8; i++) {
        vals[i] = __expf(vals[i] - vmax);
        sum += vals[i];
    }
    sum = block_reduce_sum(sum);
    float inv = 1.f / sum;
#pragma unroll
    for (int i = 0; i < 8; i++) r[tid + i * 256] = vals[i] * inv;
}

// ---------------- launch -----------------------------------------------------
extern "C" void kernel_launch(void* const* d_in, const int* in_sizes, int n_in,
                              void* d_out, int out_size) {
    const float* x     = (const float*)d_in[0];
    const float* ctx   = (const float*)d_in[1];
    const float* wq    = (const float*)d_in[2];
    const float* bq    = (const float*)d_in[3];
    const float* wk    = (const float*)d_in[4];
    const float* bk    = (const float*)d_in[5];
    const float* wv    = (const float*)d_in[6];
    const float* bv    = (const float*)d_in[7];
    const float* wo    = (const float*)d_in[8];
    const float* bo    = (const float*)d_in[9];
    const float* w1    = (const float*)d_in[10];
    const float* b1    = (const float*)d_in[11];
    const float* w2    = (const float*)d_in[12];
    const float* b2    = (const float*)d_in[13];
    const float* qn_w  = (const float*)d_in[14];
    const float* qn_b  = (const float*)d_in[15];
    const float* kvn_w = (const float*)d_in[16];
    const float* kvn_b = (const float*)d_in[17];
    const float* pn_w  = (const float*)d_in[18];
    const float* pn_b  = (const float*)d_in[19];
    float* out = (float*)d_out;

    float *xq, *kv, *q, *k, *v, *s, *o, *x1, *hln, *h1;
    cudaGetSymbolAddress((void**)&xq, g_xq);
    cudaGetSymbolAddress((void**)&kv, g_kv);
    cudaGetSymbolAddress((void**)&q, g_q);
    cudaGetSymbolAddress((void**)&k, g_k);
    cudaGetSymbolAddress((void**)&v, g_v);
    cudaGetSymbolAddress((void**)&s, g_s);
    cudaGetSymbolAddress((void**)&o, g_o);
    cudaGetSymbolAddress((void**)&x1, g_x1);
    cudaGetSymbolAddress((void**)&hln, g_hln);
    cudaGetSymbolAddress((void**)&h1, g_h1);

    // 1. pre-norms
    layernorm_kernel<DD><<<NT, 256>>>(x, qn_w, qn_b, xq);
    layernorm_kernel<CC><<<MT, 256>>>(ctx, kvn_w, kvn_b, kv);

    // 2. Q/K/V projections
    gemm_kernel<1, 0, 0, 0><<<dim3(DD / BN, NT / BM, 1), 256>>>(
        xq, wq, bq, nullptr, q, DD, DD, DD, DD, 0, 0, 0, 1.f);
    gemm_kernel<1, 0, 0, 0><<<dim3(DD / BN, MT / BM, 1), 256>>>(
        kv, wk, bk, nullptr, k, CC, CC, DD, DD, 0, 0, 0, 1.f);
    gemm_kernel<1, 0, 0, 0><<<dim3(DD / BN, MT / BM, 1), 256>>>(
        kv, wv, bv, nullptr, v, CC, CC, DD, DD, 0, 0, 0, 1.f);

    // 3. scores S[h] = Q_h @ K_h^T / sqrt(HD)   (batched over heads via z)
    gemm_kernel<0, 0, 0, 1><<<dim3(MT / BN, NT / BM, NH), 256>>>(
        q, k, nullptr, nullptr, s, HD, DD, DD, MT,
        (long long)HD, (long long)HD, (long long)NT * MT, 0.125f);

    // 4. softmax over context dim
    softmax_kernel<<<NH * NT, 256>>>(s);

    // 5. O[h] = S[h] @ V_h, written interleaved to [n, h*HD+d]
    gemm_kernel<0, 0, 0, 0><<<dim3(HD / BN, NT / BM, NH), 256>>>(
        s, v, nullptr, nullptr, o, MT, MT, DD, DD,
        (long long)NT * MT, (long long)HD, (long long)HD, 1.f);

    // 6. x1 = o @ wo + bo + x
    gemm_kernel<1, 1, 0, 0><<<dim3(DD / BN, NT / BM, 1), 256>>>(
        o, wo, bo, x, x1, DD, DD, DD, DD, 0, 0, 0, 1.f);

    // 7. MLP block
    layernorm_kernel<DD><<<NT, 256>>>(x1, pn_w, pn_b, hln);
    gemm_kernel<1, 0, 1, 0><<<dim3(FF / BN, NT / BM, 1), 256>>>(
        hln, w1, b1, nullptr, h1, DD, DD, FF, FF, 0, 0, 0, 1.f);
    gemm_kernel<1, 1, 0, 0><<<dim3(DD / BN, NT / BM, 1), 256>>>(
        h1, w2, b2, x1, out, FF, FF, DD, DD, 0, 0, 0, 1.f);
}

// round 3
// speedup vs baseline: 1.1702x; 1.1702x over previous
#include <cuda_runtime.h>
#include <cuda_bf16.h>
#include <math.h>
#include <stdint.h>

#define NT 2048
#define DD 1024
#define CC 768
#define NH 16
#define HD 64
#define MT 2048
#define FF 4096

// ---------------- scratch ----------------------------------------------------
__device__ float g_xq[NT * DD];
__device__ float g_kv[MT * CC];
__device__ float g_q[NT * DD];
__device__ float g_k[MT * DD];
__device__ float g_v[MT * DD];
__device__ float g_s[(size_t)NH * NT * MT];
__device__ float g_o[NT * DD];
__device__ float g_x1[NT * DD];
__device__ float g_hln[NT * DD];
__device__ float g_h1[(size_t)NT * FF];

// ---------------- helpers ----------------------------------------------------
__device__ __forceinline__ uint32_t smem_addr_u32(const void* p) {
    uint32_t a;
    asm("{ .reg .u64 t; cvta.to.shared.u64 t, %1; cvt.u32.u64 %0, t; }" : "=r"(a) : "l"(p));
    return a;
}
__device__ __forceinline__ void ldsm4(uint32_t* r, uint32_t addr) {
    asm volatile("ldmatrix.sync.aligned.m8n8.x4.shared.b16 {%0,%1,%2,%3}, [%4];"
                 : "=r"(r[0]), "=r"(r[1]), "=r"(r[2]), "=r"(r[3]) : "r"(addr));
}
__device__ __forceinline__ void mma_bf16(float* d, const uint32_t* a, const uint32_t* b) {
    asm volatile(
        "mma.sync.aligned.m16n8k16.row.col.f32.bf16.bf16.f32 "
        "{%0,%1,%2,%3}, {%4,%5,%6,%7}, {%8,%9}, {%0,%1,%2,%3};"
        : "+f"(d[0]), "+f"(d[1]), "+f"(d[2]), "+f"(d[3])
        : "r"(a[0]), "r"(a[1]), "r"(a[2]), "r"(a[3]), "r"(b[0]), "r"(b[1]));
}
// split fp32 pair into hi/lo bf16 packed words
__device__ __forceinline__ void split2(float x, float y, uint32_t& h, uint32_t& l) {
    __nv_bfloat16 xh = __float2bfloat16(x), yh = __float2bfloat16(y);
    float xr = x - __bfloat162float(xh);
    float yr = y - __bfloat162float(yh);
    __nv_bfloat16 xl = __float2bfloat16(xr), yl = __float2bfloat16(yr);
    h = (uint32_t)__bfloat16_as_ushort(xh) | ((uint32_t)__bfloat16_as_ushort(yh) << 16);
    l = (uint32_t)__bfloat16_as_ushort(xl) | ((uint32_t)__bfloat16_as_ushort(yl) << 16);
}

// ---------------- block reductions -------------------------------------------
__device__ __forceinline__ float block_reduce_sum(float v) {
    __shared__ float sh[8];
    int tid = threadIdx.x;
#pragma unroll
    for (int o = 16; o > 0; o >>= 1) v += __shfl_down_sync(0xffffffffu, v, o);
    if ((tid & 31) == 0) sh[tid >> 5] = v;
    __syncthreads();
    if (tid < 32) {
        v = (tid < 8) ? sh[tid] : 0.f;
#pragma unroll
        for (int o = 4; o > 0; o >>= 1) v += __shfl_down_sync(0xffffffffu, v, o);
        if (tid == 0) sh[0] = v;
    }
    __syncthreads();
    float r = sh[0];
    __syncthreads();
    return r;
}
__device__ __forceinline__ float block_reduce_max(float v) {
    __shared__ float sh[8];
    int tid = threadIdx.x;
#pragma unroll
    for (int o = 16; o > 0; o >>= 1) v = fmaxf(v, __shfl_down_sync(0xffffffffu, v, o));
    if ((tid & 31) == 0) sh[tid >> 5] = v;
    __syncthreads();
    if (tid < 32) {
        v = (tid < 8) ? sh[tid] : -INFINITY;
#pragma unroll
        for (int o = 4; o > 0; o >>= 1) v = fmaxf(v, __shfl_down_sync(0xffffffffu, v, o));
        if (tid == 0) sh[0] = v;
    }
    __syncthreads();
    float r = sh[0];
    __syncthreads();
    return r;
}

// ---------------- layernorm --------------------------------------------------
template <int DIM>
__global__ __launch_bounds__(256) void layernorm_kernel(
    const float* __restrict__ x, const float* __restrict__ w,
    const float* __restrict__ b, float* __restrict__ o) {
    const float* xr = x + (size_t)blockIdx.x * DIM;
    float* orow = o + (size_t)blockIdx.x * DIM;
    float s = 0.f;
    for (int i = threadIdx.x; i < DIM; i += 256) s += xr[i];
    float mean = block_reduce_sum(s) * (1.f / DIM);
    float vv = 0.f;
    for (int i = threadIdx.x; i < DIM; i += 256) {
        float c = xr[i] - mean;
        vv += c * c;
    }
    float var = block_reduce_sum(vv) * (1.f / DIM);
    float inv = rsqrtf(var + 1e-12f);
    for (int i = threadIdx.x; i < DIM; i += 256)
        orow[i] = (xr[i] - mean) * inv * w[i] + b[i];
}

// ---------------- softmax ----------------------------------------------------
__global__ __launch_bounds__(256) void softmax_kernel(float* __restrict__ S) {
    float* r = S + (size_t)blockIdx.x * MT;
    int tid = threadIdx.x;
    float vals[8];
    float vmax = -INFINITY;
#pragma unroll
    for (int i = 0; i < 8; i++) {
        vals[i] = r[tid + i * 256];
        vmax = fmaxf(vmax, vals[i]);
    }
    vmax = block_reduce_max(vmax);
    float sum = 0.f;
#pragma unroll
    for (int i = 0; i < 8; i++) {
        vals[i] = __expf(vals[i] - vmax);
        sum += vals[i];
    }
    sum = block_reduce_sum(sum);
    float inv = 1.f / sum;
#pragma unroll
    for (int i = 0; i < 8; i++) r[tid + i * 256] = vals[i] * inv;
}

// ---------------- split-bf16 mma.sync GEMM -----------------------------------
// C[128 x BN_] = alpha*A@B(^T) (+bias)(+res)(gelu); z-batched via strides.
// A: [M,K] row-major. TRANS_B=1: B [N,K] row-major (requires BN_=128).
// TRANS_B=0: B [K,N] row-major (transposed on load).
template <int HAS_BIAS, int HAS_RES, int DO_GELU, int TRANS_B, int BN_>
__global__ __launch_bounds__(256, 1) void tc_gemm(
    const float* __restrict__ A, const float* __restrict__ B,
    const float* __restrict__ bias, const float* __restrict__ Res,
    float* __restrict__ C, int K, int lda, int ldb, int ldc,
    long long sA, long long sB, long long sC, float alpha) {
    constexpr int ROWE = 40;               // padded bf16 elems per row
    constexpr int ROWB = ROWE * 2;         // 80 bytes
    constexpr int ASZ = 128 * ROWB;        // A hi tile bytes
    constexpr int BSZ = BN_ * ROWB;
    constexpr int STAGE = 2 * ASZ + 2 * BSZ;
    constexpr int WN = BN_ / 4;            // per-warp n extent
    constexpr int NT8 = WN / 8;            // n8 tiles per warp
    constexpr int NX4 = WN / 16;           // B ldmatrix.x4 per k-step

    extern __shared__ char smem[];
    const int tid = threadIdx.x;
    const int wid = tid >> 5, lane = tid & 31;
    const int wm = wid & 1, wn = wid >> 1;
    const uint32_t sbase = smem_addr_u32(smem);

    const float* Ab = A + (size_t)blockIdx.z * sA + (size_t)blockIdx.y * 128 * lda;
    const float* Bb;
    if (TRANS_B)
        Bb = B + (size_t)blockIdx.z * sB + (size_t)blockIdx.x * BN_ * ldb;
    else
        Bb = B + (size_t)blockIdx.z * sB + (size_t)blockIdx.x * BN_;
    const size_t c_off =
        (size_t)blockIdx.z * sC + (size_t)blockIdx.y * 128 * ldc + (size_t)blockIdx.x * BN_;

    // ---- loaders -------------------------------------------------------------
    const int ar = tid >> 1;               // A row (0..127)
    const int ahalf = (tid & 1) * 16;      // k sub-offset
    float4 pa[4];
    constexpr int NPB4 = BN_ / 4;
    constexpr int BIT = (32 * NPB4) / 256; // float4/thread for TRANS_B=0
    float4 pb[TRANS_B ? 4 : BIT];

    auto ldgA = [&](int k0) {
        const float* p = Ab + (size_t)ar * lda + k0 + ahalf;
#pragma unroll
        for (int i = 0; i < 4; i++) pa[i] = *(const float4*)(p + i * 4);
    };
    auto ldgB = [&](int k0) {
        if (TRANS_B) {
            const float* p = Bb + (size_t)ar * ldb + k0 + ahalf;
#pragma unroll
            for (int i = 0; i < 4; i++) pb[i] = *(const float4*)(p + i * 4);
        } else {
#pragma unroll
            for (int i = 0; i < BIT; i++) {
                int idx = i * 256 + tid;
                int kr = idx / NPB4, n4 = idx % NPB4;
                pb[i] = *(const float4*)(Bb + (size_t)(k0 + kr) * ldb + n4 * 4);
            }
        }
    };
    auto stsA = [&](int b) {
        uint32_t hw[8], lw[8];
#pragma unroll
        for (int i = 0; i < 4; i++) {
            const float* f = (const float*)&pa[i];
            split2(f[0], f[1], hw[i * 2], lw[i * 2]);
            split2(f[2], f[3], hw[i * 2 + 1], lw[i * 2 + 1]);
        }
        char* base = smem + b * STAGE;
        uint32_t off = (uint32_t)ar * ROWB + (uint32_t)ahalf * 2;
        *(uint4*)(base + off) = *(uint4*)hw;
        *(uint4*)(base + off + 16) = *(uint4*)(hw + 4);
        *(uint4*)(base + ASZ + off) = *(uint4*)lw;
        *(uint4*)(base + ASZ + off + 16) = *(uint4*)(lw + 4);
    };
    auto stsB = [&](int b) {
        char* bh = smem + b * STAGE + 2 * ASZ;
        char* bl = bh + BSZ;
        if (TRANS_B) {
            uint32_t hw[8], lw[8];
#pragma unroll
            for (int i = 0; i < 4; i++) {
                const float* f = (const float*)&pb[i];
                split2(f[0], f[1], hw[i * 2], lw[i * 2]);
                split2(f[2], f[3], hw[i * 2 + 1], lw[i * 2 + 1]);
            }
            uint32_t off = (uint32_t)ar * ROWB + (uint32_t)ahalf * 2;
            *(uint4*)(bh + off) = *(uint4*)hw;
            *(uint4*)(bh + off + 16) = *(uint4*)(hw + 4);
            *(uint4*)(bl + off) = *(uint4*)lw;
            *(uint4*)(bl + off + 16) = *(uint4*)(lw + 4);
        } else {
#pragma unroll
            for (int i = 0; i < BIT; i++) {
                int idx = i * 256 + tid;
                int kr = idx / NPB4, n4 = idx % NPB4;
                const float* f = (const float*)&pb[i];
#pragma unroll
                for (int j = 0; j < 4; j++) {
                    __nv_bfloat16 h = __float2bfloat16(f[j]);
                    float rres = f[j] - __bfloat162float(h);
                    __nv_bfloat16 l = __float2bfloat16(rres);
                    uint32_t off = (uint32_t)(n4 * 4 + j) * ROWB + (uint32_t)kr * 2;
                    *(uint16_t*)(bh + off) = __bfloat16_as_ushort(h);
                    *(uint16_t*)(bl + off) = __bfloat16_as_ushort(l);
                }
            }
        }
    };

    // ---- accumulators --------------------------------------------------------
    float acc[4][NT8][4];
#pragma unroll
    for (int i = 0; i < 4; i++)
#pragma unroll
        for (int j = 0; j < NT8; j++)
#pragma unroll
            for (int q = 0; q < 4; q++) acc[i][j][q] = 0.f;

    const int lr = lane & 15, lc8 = ((lane >> 4) << 3);
    const int bn = (lane & 7) + ((lane >> 4) << 3);
    const int bc8 = ((lane >> 3) & 1) << 3;

    auto domma = [&](int b) {
        const uint32_t ah = sbase + b * STAGE;
        const uint32_t al = ah + ASZ;
        const uint32_t bh = al + ASZ;
        const uint32_t bl = bh + BSZ;
#pragma unroll
        for (int kk = 0; kk < 2; kk++) {
            uint32_t ahf[4][4], alf[4][4], bhf[NX4][4], blf[NX4][4];
#pragma unroll
            for (int mi = 0; mi < 4; mi++)
                ldsm4(ahf[mi], ah + (uint32_t)((wm * 64 + mi * 16 + lr) * ROWB +
                                              (kk * 16 + lc8) * 2));
#pragma unroll
            for (int nj = 0; nj < NX4; nj++)
                ldsm4(bhf[nj], bh + (uint32_t)((wn * WN + nj * 16 + bn) * ROWB +
                                               (kk * 16 + bc8) * 2));
#pragma unroll
            for (int mi = 0; mi < 4; mi++)
#pragma unroll
                for (int nj = 0; nj < NX4; nj++) {
                    mma_bf16(acc[mi][2 * nj], ahf[mi], &bhf[nj][0]);
                    mma_bf16(acc[mi][2 * nj + 1], ahf[mi], &bhf[nj][2]);
                }
#pragma unroll
            for (int nj = 0; nj < NX4; nj++)
                ldsm4(blf[nj], bl + (uint32_t)((wn * WN + nj * 16 + bn) * ROWB +
                                               (kk * 16 + bc8) * 2));
#pragma unroll
            for (int mi = 0; mi < 4; mi++)
#pragma unroll
                for (int nj = 0; nj < NX4; nj++) {
                    mma_bf16(acc[mi][2 * nj], ahf[mi], &blf[nj][0]);
                    mma_bf16(acc[mi][2 * nj + 1], ahf[mi], &blf[nj][2]);
                }
#pragma unroll
            for (int mi = 0; mi < 4; mi++)
                ldsm4(alf[mi], al + (uint32_t)((wm * 64 + mi * 16 + lr) * ROWB +
                                               (kk * 16 + lc8) * 2));
#pragma unroll
            for (int mi = 0; mi < 4; mi++)
#pragma unroll
                for (int nj = 0; nj < NX4; nj++) {
                    mma_bf16(acc[mi][2 * nj], alf[mi], &bhf[nj][0]);
                    mma_bf16(acc[mi][2 * nj + 1], alf[mi], &bhf[nj][2]);
                }
        }
    };

    // ---- pipelined mainloop --------------------------------------------------
    const int T = K >> 5;
    ldgA(0);
    ldgB(0);
    stsA(0);
    stsB(0);
    __syncthreads();
#pragma unroll 1
    for (int t = 0; t < T; t++) {
        if (t + 1 < T) {
            ldgA((t + 1) * 32);
            ldgB((t + 1) * 32);
        }
        domma(t & 1);
        if (t + 1 < T) {
            stsA((t + 1) & 1);
            stsB((t + 1) & 1);
        }
        __syncthreads();
    }

    // ---- epilogue ------------------------------------------------------------
    const int g = lane >> 2, tg = lane & 3;
#pragma unroll
    for (int mi = 0; mi < 4; mi++) {
#pragma unroll
        for (int n8 = 0; n8 < NT8; n8++) {
            int col = wn * WN + n8 * 8 + tg * 2;
#pragma unroll
            for (int rr = 0; rr < 2; rr++) {
                int row = wm * 64 + mi * 16 + g + rr * 8;
                float v0 = acc[mi][n8][rr * 2] * alpha;
                float v1 = acc[mi][n8][rr * 2 + 1] * alpha;
                if (HAS_BIAS) {
                    v0 += bias[blockIdx.x * BN_ + col];
                    v1 += bias[blockIdx.x * BN_ + col + 1];
                }
                if (HAS_RES) {
                    const float* rp = Res + c_off + (size_t)row * ldc + col;
                    v0 += rp[0];
                    v1 += rp[1];
                }
                if (DO_GELU) {
                    float i0 = 0.7978845608028654f * (v0 + 0.044715f * v0 * v0 * v0);
                    v0 = 0.5f * v0 * (1.f + tanhf(i0));
                    float i1 = 0.7978845608028654f * (v1 + 0.044715f * v1 * v1 * v1);
                    v1 = 0.5f * v1 * (1.f + tanhf(i1));
                }
                float2 o2 = make_float2(v0, v1);
                *(float2*)(C + c_off + (size_t)row * ldc + col) = o2;
            }
        }
    }
}

// ---------------- launch -----------------------------------------------------
static inline size_t tc_smem_bytes(int BN) {
    return 2 * (2 * (size_t)128 * 80 + 2 * (size_t)BN * 80);
}

extern "C" void kernel_launch(void* const* d_in, const int* in_sizes, int n_in,
                              void* d_out, int out_size) {
    const float* x     = (const float*)d_in[0];
    const float* ctx   = (const float*)d_in[1];
    const float* wq    = (const float*)d_in[2];
    const float* bq    = (const float*)d_in[3];
    const float* wk    = (const float*)d_in[4];
    const float* bk    = (const float*)d_in[5];
    const float* wv    = (const float*)d_in[6];
    const float* bv    = (const float*)d_in[7];
    const float* wo    = (const float*)d_in[8];
    const float* bo    = (const float*)d_in[9];
    const float* w1    = (const float*)d_in[10];
    const float* b1    = (const float*)d_in[11];
    const float* w2    = (const float*)d_in[12];
    const float* b2    = (const float*)d_in[13];
    const float* qn_w  = (const float*)d_in[14];
    const float* qn_b  = (const float*)d_in[15];
    const float* kvn_w = (const float*)d_in[16];
    const float* kvn_b = (const float*)d_in[17];
    const float* pn_w  = (const float*)d_in[18];
    const float* pn_b  = (const float*)d_in[19];
    float* out = (float*)d_out;

    float *xq, *kv, *q, *k, *v, *s, *o, *x1, *hln, *h1;
    cudaGetSymbolAddress((void**)&xq, g_xq);
    cudaGetSymbolAddress((void**)&kv, g_kv);
    cudaGetSymbolAddress((void**)&q, g_q);
    cudaGetSymbolAddress((void**)&k, g_k);
    cudaGetSymbolAddress((void**)&v, g_v);
    cudaGetSymbolAddress((void**)&s, g_s);
    cudaGetSymbolAddress((void**)&o, g_o);
    cudaGetSymbolAddress((void**)&x1, g_x1);
    cudaGetSymbolAddress((void**)&hln, g_hln);
    cudaGetSymbolAddress((void**)&h1, g_h1);

    const size_t SM128 = tc_smem_bytes(128);  // 81920
    const size_t SM64  = tc_smem_bytes(64);   // 61440
    cudaFuncSetAttribute((const void*)tc_gemm<1, 0, 0, 0, 128>,
                         cudaFuncAttributeMaxDynamicSharedMemorySize, (int)SM128);
    cudaFuncSetAttribute((const void*)tc_gemm<0, 0, 0, 1, 128>,
                         cudaFuncAttributeMaxDynamicSharedMemorySize, (int)SM128);
    cudaFuncSetAttribute((const void*)tc_gemm<0, 0, 0, 0, 64>,
                         cudaFuncAttributeMaxDynamicSharedMemorySize, (int)SM64);
    cudaFuncSetAttribute((const void*)tc_gemm<1, 1, 0, 0, 128>,
                         cudaFuncAttributeMaxDynamicSharedMemorySize, (int)SM128);
    cudaFuncSetAttribute((const void*)tc_gemm<1, 0, 1, 0, 128>,
                         cudaFuncAttributeMaxDynamicSharedMemorySize, (int)SM128);

    // 1. pre-norms
    layernorm_kernel<DD><<<NT, 256>>>(x, qn_w, qn_b, xq);
    layernorm_kernel<CC><<<MT, 256>>>(ctx, kvn_w, kvn_b, kv);

    // 2. Q/K/V projections
    tc_gemm<1, 0, 0, 0, 128><<<dim3(DD / 128, NT / 128, 1), 256, SM128>>>(
        xq, wq, bq, nullptr, q, DD, DD, DD, DD, 0, 0, 0, 1.f);
    tc_gemm<1, 0, 0, 0, 128><<<dim3(DD / 128, MT / 128, 1), 256, SM128>>>(
        kv, wk, bk, nullptr, k, CC, CC, DD, DD, 0, 0, 0, 1.f);
    tc_gemm<1, 0, 0, 0, 128><<<dim3(DD / 128, MT / 128, 1), 256, SM128>>>(
        kv, wv, bv, nullptr, v, CC, CC, DD, DD, 0, 0, 0, 1.f);

    // 3. S[h] = Q_h @ K_h^T / 8
    tc_gemm<0, 0, 0, 1, 128><<<dim3(MT / 128, NT / 128, NH), 256, SM128>>>(
        q, k, nullptr, nullptr, s, HD, DD, DD, MT,
        (long long)HD, (long long)HD, (long long)NT * MT, 0.125f);

    // 4. softmax
    softmax_kernel<<<NH * NT, 256>>>(s);

    // 5. O[h] = S[h] @ V_h
    tc_gemm<0, 0, 0, 0, 64><<<dim3(1, NT / 128, NH), 256, SM64>>>(
        s, v, nullptr, nullptr, o, MT, MT, DD, DD,
        (long long)NT * MT, (long long)HD, (long long)HD, 1.f);

    // 6. x1 = o @ wo + bo + x
    tc_gemm<1, 1, 0, 0, 128><<<dim3(DD / 128, NT / 128, 1), 256, SM128>>>(
        o, wo, bo, x, x1, DD, DD, DD, DD, 0, 0, 0, 1.f);

    // 7. MLP
    layernorm_kernel<DD><<<NT, 256>>>(x1, pn_w, pn_b, hln);
    tc_gemm<1, 0, 1, 0, 128><<<dim3(FF / 128, NT / 128, 1), 256, SM128>>>(
        hln, w1, b1, nullptr, h1, DD, DD, FF, FF, 0, 0, 0, 1.f);
    tc_gemm<1, 1, 0, 0, 128><<<dim3(DD / 128, NT / 128, 1), 256, SM128>>>(
        h1, w2, b2, x1, out, FF, FF, DD, DD, 0, 0, 0, 1.f);
}

// round 4
// speedup vs baseline: 1.6062x; 1.3725x over previous
#include <cuda_runtime.h>
#include <cuda_bf16.h>
#include <math.h>
#include <stdint.h>

#define NT 2048
#define DD 1024
#define CC 768
#define NH 16
#define HD 64
#define MT 2048
#define FF 4096

// ---------------- scratch ----------------------------------------------------
__device__ float g_xq[NT * DD];
__device__ float g_kv[MT * CC];
__device__ float g_q[NT * DD];
__device__ float g_k[MT * DD];
__device__ float g_v[MT * DD];
__device__ float g_o[NT * DD];
__device__ float g_x1[NT * DD];
__device__ float g_hln[NT * DD];
__device__ float g_h1[(size_t)NT * FF];

// ---------------- helpers ----------------------------------------------------
__device__ __forceinline__ uint32_t smem_addr_u32(const void* p) {
    uint32_t a;
    asm("{ .reg .u64 t; cvta.to.shared.u64 t, %1; cvt.u32.u64 %0, t; }" : "=r"(a) : "l"(p));
    return a;
}
__device__ __forceinline__ void ldsm4(uint32_t* r, uint32_t addr) {
    asm volatile("ldmatrix.sync.aligned.m8n8.x4.shared.b16 {%0,%1,%2,%3}, [%4];"
                 : "=r"(r[0]), "=r"(r[1]), "=r"(r[2]), "=r"(r[3]) : "r"(addr));
}
__device__ __forceinline__ void ldsm4t(uint32_t* r, uint32_t addr) {
    asm volatile("ldmatrix.sync.aligned.m8n8.x4.trans.shared.b16 {%0,%1,%2,%3}, [%4];"
                 : "=r"(r[0]), "=r"(r[1]), "=r"(r[2]), "=r"(r[3]) : "r"(addr));
}
__device__ __forceinline__ void mma_bf16(float* d, const uint32_t* a, const uint32_t* b) {
    asm volatile(
        "mma.sync.aligned.m16n8k16.row.col.f32.bf16.bf16.f32 "
        "{%0,%1,%2,%3}, {%4,%5,%6,%7}, {%8,%9}, {%0,%1,%2,%3};"
        : "+f"(d[0]), "+f"(d[1]), "+f"(d[2]), "+f"(d[3])
        : "r"(a[0]), "r"(a[1]), "r"(a[2]), "r"(a[3]), "r"(b[0]), "r"(b[1]));
}
__device__ __forceinline__ void split2(float x, float y, uint32_t& h, uint32_t& l) {
    __nv_bfloat16 xh = __float2bfloat16(x), yh = __float2bfloat16(y);
    float xr = x - __bfloat162float(xh);
    float yr = y - __bfloat162float(yh);
    __nv_bfloat16 xl = __float2bfloat16(xr), yl = __float2bfloat16(yr);
    h = (uint32_t)__bfloat16_as_ushort(xh) | ((uint32_t)__bfloat16_as_ushort(yh) << 16);
    l = (uint32_t)__bfloat16_as_ushort(xl) | ((uint32_t)__bfloat16_as_ushort(yl) << 16);
}

// ---------------- block reductions -------------------------------------------
__device__ __forceinline__ float block_reduce_sum(float v) {
    __shared__ float sh[8];
    int tid = threadIdx.x;
#pragma unroll
    for (int o = 16; o > 0; o >>= 1) v += __shfl_down_sync(0xffffffffu, v, o);
    if ((tid & 31) == 0) sh[tid >> 5] = v;
    __syncthreads();
    if (tid < 32) {
        v = (tid < 8) ? sh[tid] : 0.f;
#pragma unroll
        for (int o = 4; o > 0; o >>= 1) v += __shfl_down_sync(0xffffffffu, v, o);
        if (tid == 0) sh[0] = v;
    }
    __syncthreads();
    float r = sh[0];
    __syncthreads();
    return r;
}

// ---------------- layernorm --------------------------------------------------
template <int DIM>
__global__ __launch_bounds__(256) void layernorm_kernel(
    const float* __restrict__ x, const float* __restrict__ w,
    const float* __restrict__ b, float* __restrict__ o) {
    const float* xr = x + (size_t)blockIdx.x * DIM;
    float* orow = o + (size_t)blockIdx.x * DIM;
    float s = 0.f;
    for (int i = threadIdx.x; i < DIM; i += 256) s += xr[i];
    float mean = block_reduce_sum(s) * (1.f / DIM);
    float vv = 0.f;
    for (int i = threadIdx.x; i < DIM; i += 256) {
        float c = xr[i] - mean;
        vv += c * c;
    }
    float var = block_reduce_sum(vv) * (1.f / DIM);
    float inv = rsqrtf(var + 1e-12f);
    for (int i = threadIdx.x; i < DIM; i += 256)
        orow[i] = (xr[i] - mean) * inv * w[i] + b[i];
}

// ---------------- split-bf16 mma.sync GEMM (v2) -------------------------------
// C[128 x 128] = A@B (+bias)(+res)(gelu). A [M,K] row-major (lda=K),
// B [K,N] row-major (ldb=N=ldc). 8 warps, warp tile 64x32, 2 CTAs/SM.
template <int HAS_BIAS, int HAS_RES, int DO_GELU>
__global__ __launch_bounds__(256, 2) void tc_gemm(
    const float* __restrict__ A, const float* __restrict__ B,
    const float* __restrict__ bias, const float* __restrict__ Res,
    float* __restrict__ C, int K, int ldb) {
    constexpr int RA = 80;              // A row pitch bytes (32 bf16 + pad)
    constexpr int RB = 272;             // B row pitch bytes (128 bf16 + pad)
    constexpr int ASZ = 128 * RA;       // 10240
    constexpr int BSZ = 32 * RB;        // 8704
    constexpr int STAGE = 2 * ASZ + 2 * BSZ;  // 37888

    extern __shared__ char sm[];
    const int tid = threadIdx.x, lane = tid & 31, wid = tid >> 5;
    const int wm = wid & 1, wn = wid >> 1;
    const uint32_t sb = smem_addr_u32(sm);

    const float* Ab = A + (size_t)blockIdx.y * 128 * K;
    const float* Bb = B + (size_t)blockIdx.x * 128;
    const size_t c0 = (size_t)blockIdx.y * 128 * ldb + (size_t)blockIdx.x * 128;

    auto loadA = [&](int k0, int buf) {
        char* d = sm + buf * STAGE;
        int r = tid >> 1, h16 = (tid & 1) * 16;
        const float* p = Ab + (size_t)r * K + k0 + h16;
        uint32_t hw[8], lw[8];
#pragma unroll
        for (int i = 0; i < 4; i++) {
            float4 f = *(const float4*)(p + i * 4);
            split2(f.x, f.y, hw[2 * i], lw[2 * i]);
            split2(f.z, f.w, hw[2 * i + 1], lw[2 * i + 1]);
        }
        uint32_t off = (uint32_t)r * RA + (uint32_t)h16 * 2;
        *(uint4*)(d + off) = *(uint4*)hw;
        *(uint4*)(d + off + 16) = *(uint4*)(hw + 4);
        *(uint4*)(d + ASZ + off) = *(uint4*)lw;
        *(uint4*)(d + ASZ + off + 16) = *(uint4*)(lw + 4);
    };
    auto loadB = [&](int k0, int buf) {
        char* dh = sm + buf * STAGE + 2 * ASZ;
        char* dl = dh + BSZ;
#pragma unroll
        for (int j = 0; j < 4; j++) {
            int idx = tid + j * 256;
            int r = idx >> 5, c4 = idx & 31;
            float4 f = *(const float4*)(Bb + (size_t)(k0 + r) * ldb + c4 * 4);
            uint32_t h0, l0, h1, l1;
            split2(f.x, f.y, h0, l0);
            split2(f.z, f.w, h1, l1);
            uint32_t off = (uint32_t)r * RB + (uint32_t)c4 * 8;
            *(uint2*)(dh + off) = make_uint2(h0, h1);
            *(uint2*)(dl + off) = make_uint2(l0, l1);
        }
    };

    float acc[4][4][4];
#pragma unroll
    for (int i = 0; i < 4; i++)
#pragma unroll
        for (int j = 0; j < 4; j++)
#pragma unroll
            for (int q = 0; q < 4; q++) acc[i][j][q] = 0.f;

    const int lr = lane & 15;
    const int ac8 = (lane >> 4) << 3;

    auto domma = [&](int buf) {
        const uint32_t ah = sb + buf * STAGE;
        const uint32_t al = ah + ASZ;
        const uint32_t bh = al + ASZ;
        const uint32_t bl = bh + BSZ;
#pragma unroll
        for (int kk = 0; kk < 2; kk++) {
            uint32_t bhf[2][4], blf[2][4];
#pragma unroll
            for (int nb = 0; nb < 2; nb++) {
                uint32_t boff = (uint32_t)(kk * 16 + lr) * RB +
                                (uint32_t)(wn * 32 + nb * 16 + ac8) * 2;
                ldsm4t(bhf[nb], bh + boff);
                ldsm4t(blf[nb], bl + boff);
            }
#pragma unroll
            for (int mi = 0; mi < 4; mi++) {
                uint32_t aoff = (uint32_t)(wm * 64 + mi * 16 + lr) * RA +
                                (uint32_t)(kk * 16 + ac8) * 2;
                uint32_t ahf[4], alf[4];
                ldsm4(ahf, ah + aoff);
#pragma unroll
                for (int nb = 0; nb < 2; nb++) {
                    mma_bf16(acc[mi][2 * nb], ahf, &bhf[nb][0]);
                    mma_bf16(acc[mi][2 * nb + 1], ahf, &bhf[nb][2]);
                    mma_bf16(acc[mi][2 * nb], ahf, &blf[nb][0]);
                    mma_bf16(acc[mi][2 * nb + 1], ahf, &blf[nb][2]);
                }
                ldsm4(alf, al + aoff);
#pragma unroll
                for (int nb = 0; nb < 2; nb++) {
                    mma_bf16(acc[mi][2 * nb], alf, &bhf[nb][0]);
                    mma_bf16(acc[mi][2 * nb + 1], alf, &bhf[nb][2]);
                }
            }
        }
    };

    const int T = K >> 5;
    loadA(0, 0);
    loadB(0, 0);
    __syncthreads();
#pragma unroll 1
    for (int t = 0; t < T; t++) {
        domma(t & 1);
        if (t + 1 < T) {
            loadA((t + 1) * 32, (t + 1) & 1);
            loadB((t + 1) * 32, (t + 1) & 1);
        }
        __syncthreads();
    }

    // epilogue
    const int g = lane >> 2, q = lane & 3;
#pragma unroll
    for (int mi = 0; mi < 4; mi++)
#pragma unroll
        for (int nj = 0; nj < 4; nj++) {
            int col = wn * 32 + nj * 8 + q * 2;
#pragma unroll
            for (int rr = 0; rr < 2; rr++) {
                int row = wm * 64 + mi * 16 + g + rr * 8;
                float v0 = acc[mi][nj][rr * 2];
                float v1 = acc[mi][nj][rr * 2 + 1];
                if (HAS_BIAS) {
                    v0 += bias[blockIdx.x * 128 + col];
                    v1 += bias[blockIdx.x * 128 + col + 1];
                }
                if (HAS_RES) {
                    const float* rp = Res + c0 + (size_t)row * ldb + col;
                    v0 += rp[0];
                    v1 += rp[1];
                }
                if (DO_GELU) {
                    float i0 = 0.7978845608028654f * (v0 + 0.044715f * v0 * v0 * v0);
                    v0 = 0.5f * v0 * (1.f + tanhf(i0));
                    float i1 = 0.7978845608028654f * (v1 + 0.044715f * v1 * v1 * v1);
                    v1 = 0.5f * v1 * (1.f + tanhf(i1));
                }
                *(float2*)(C + c0 + (size_t)row * ldb + col) = make_float2(v0, v1);
            }
        }
}

// ---------------- flash attention ---------------------------------------------
// grid (NT/128, NH). 8 warps, each owns 16 query rows. KV blocks of 64 keys.
// Q,K,V: [tokens, DD] with head slice at h*64. O: g_o [NT, DD] interleaved.
__global__ __launch_bounds__(256, 2) void flash_kernel(
    const float* __restrict__ Q, const float* __restrict__ K,
    const float* __restrict__ V, float* __restrict__ O) {
    constexpr int R = 144;  // 64 bf16 + 16B pad
    constexpr int QH = 0, QL = 18432, KHS = 36864, KLS = 46080, VHS = 55296, VLS = 64512;

    extern __shared__ char sm[];
    const int tid = threadIdx.x, lane = tid & 31, wid = tid >> 5;
    const int h = blockIdx.y, qb = blockIdx.x;
    const uint32_t sb = smem_addr_u32(sm);

    const float* Qg = Q + (size_t)qb * 128 * DD + h * HD;
    const float* Kg = K + (size_t)h * HD;
    const float* Vg = V + (size_t)h * HD;

    // load Q tile (128x64) hi/lo
    {
        int r = tid >> 1, half = (tid & 1) * 32;
        const float* p = Qg + (size_t)r * DD + half;
        uint32_t hw[16], lw[16];
#pragma unroll
        for (int i = 0; i < 8; i++) {
            float4 f = *(const float4*)(p + i * 4);
            split2(f.x, f.y, hw[2 * i], lw[2 * i]);
            split2(f.z, f.w, hw[2 * i + 1], lw[2 * i + 1]);
        }
        uint32_t off = (uint32_t)r * R + (uint32_t)half * 2;
#pragma unroll
        for (int i = 0; i < 4; i++) {
            *(uint4*)(sm + QH + off + i * 16) = *(uint4*)(hw + 4 * i);
            *(uint4*)(sm + QL + off + i * 16) = *(uint4*)(lw + 4 * i);
        }
    }

    float o[8][4];
#pragma unroll
    for (int i = 0; i < 8; i++)
#pragma unroll
        for (int j = 0; j < 4; j++) o[i][j] = 0.f;
    float m0 = -INFINITY, m1 = -INFINITY, l0 = 0.f, l1 = 0.f;

    const int lr = lane & 15;
    const int ac8 = (lane >> 4) << 3;
    const int bn = (lane & 7) + ((lane >> 4) << 3);
    const int bc8 = ((lane >> 3) & 1) << 3;

    for (int kb = 0; kb < MT / 64; kb++) {
        // load K/V block (64x64 each) hi/lo
        {
            int r = tid >> 2, qq = (tid & 3) * 16;
            uint32_t off = (uint32_t)r * R + (uint32_t)qq * 2;
            const float* pk = Kg + (size_t)(kb * 64 + r) * DD + qq;
            uint32_t hw[8], lw[8];
#pragma unroll
            for (int i = 0; i < 4; i++) {
                float4 f = *(const float4*)(pk + i * 4);
                split2(f.x, f.y, hw[2 * i], lw[2 * i]);
                split2(f.z, f.w, hw[2 * i + 1], lw[2 * i + 1]);
            }
            *(uint4*)(sm + KHS + off) = *(uint4*)hw;
            *(uint4*)(sm + KHS + off + 16) = *(uint4*)(hw + 4);
            *(uint4*)(sm + KLS + off) = *(uint4*)lw;
            *(uint4*)(sm + KLS + off + 16) = *(uint4*)(lw + 4);
            const float* pv = Vg + (size_t)(kb * 64 + r) * DD + qq;
#pragma unroll
            for (int i = 0; i < 4; i++) {
                float4 f = *(const float4*)(pv + i * 4);
                split2(f.x, f.y, hw[2 * i], lw[2 * i]);
                split2(f.z, f.w, hw[2 * i + 1], lw[2 * i + 1]);
            }
            *(uint4*)(sm + VHS + off) = *(uint4*)hw;
            *(uint4*)(sm + VHS + off + 16) = *(uint4*)(hw + 4);
            *(uint4*)(sm + VLS + off) = *(uint4*)lw;
            *(uint4*)(sm + VLS + off + 16) = *(uint4*)(lw + 4);
        }
        __syncthreads();

        // S = Q @ K^T (split-bf16, 3 products)
        float s[8][4];
#pragma unroll
        for (int i = 0; i < 8; i++)
#pragma unroll
            for (int j = 0; j < 4; j++) s[i][j] = 0.f;
#pragma unroll
        for (int kf = 0; kf < 4; kf++) {
            uint32_t aoff = (uint32_t)(wid * 16 + lr) * R + (uint32_t)(kf * 16 + ac8) * 2;
            uint32_t qh[4], ql[4], kh[4][4], kl[4][4];
            ldsm4(qh, sb + QH + aoff);
#pragma unroll
            for (int nb = 0; nb < 4; nb++) {
                uint32_t boff = (uint32_t)(nb * 16 + bn) * R + (uint32_t)(kf * 16 + bc8) * 2;
                ldsm4(kh[nb], sb + KHS + boff);
            }
#pragma unroll
            for (int nb = 0; nb < 4; nb++) {
                mma_bf16(s[2 * nb], qh, &kh[nb][0]);
                mma_bf16(s[2 * nb + 1], qh, &kh[nb][2]);
            }
            ldsm4(ql, sb + QL + aoff);
#pragma unroll
            for (int nb = 0; nb < 4; nb++) {
                mma_bf16(s[2 * nb], ql, &kh[nb][0]);
                mma_bf16(s[2 * nb + 1], ql, &kh[nb][2]);
            }
#pragma unroll
            for (int nb = 0; nb < 4; nb++) {
                uint32_t boff = (uint32_t)(nb * 16 + bn) * R + (uint32_t)(kf * 16 + bc8) * 2;
                ldsm4(kl[nb], sb + KLS + boff);
            }
#pragma unroll
            for (int nb = 0; nb < 4; nb++) {
                mma_bf16(s[2 * nb], qh, &kl[nb][0]);
                mma_bf16(s[2 * nb + 1], qh, &kl[nb][2]);
            }
        }

        // online softmax (raw scores scaled by 1/8 inside exp)
        float mx0 = -INFINITY, mx1 = -INFINITY;
#pragma unroll
        for (int j = 0; j < 8; j++) {
            mx0 = fmaxf(mx0, fmaxf(s[j][0], s[j][1]));
            mx1 = fmaxf(mx1, fmaxf(s[j][2], s[j][3]));
        }
        mx0 = fmaxf(mx0, __shfl_xor_sync(0xffffffffu, mx0, 1));
        mx0 = fmaxf(mx0, __shfl_xor_sync(0xffffffffu, mx0, 2));
        mx1 = fmaxf(mx1, __shfl_xor_sync(0xffffffffu, mx1, 1));
        mx1 = fmaxf(mx1, __shfl_xor_sync(0xffffffffu, mx1, 2));
        float m0n = fmaxf(m0, mx0), m1n = fmaxf(m1, mx1);
        float sc0 = __expf((m0 - m0n) * 0.125f);
        float sc1 = __expf((m1 - m1n) * 0.125f);
        m0 = m0n;
        m1 = m1n;
        float su0 = 0.f, su1 = 0.f;
#pragma unroll
        for (int j = 0; j < 8; j++) {
            s[j][0] = __expf((s[j][0] - m0) * 0.125f);
            s[j][1] = __expf((s[j][1] - m0) * 0.125f);
            s[j][2] = __expf((s[j][2] - m1) * 0.125f);
            s[j][3] = __expf((s[j][3] - m1) * 0.125f);
            su0 += s[j][0] + s[j][1];
            su1 += s[j][2] + s[j][3];
        }
        su0 += __shfl_xor_sync(0xffffffffu, su0, 1);
        su0 += __shfl_xor_sync(0xffffffffu, su0, 2);
        su1 += __shfl_xor_sync(0xffffffffu, su1, 1);
        su1 += __shfl_xor_sync(0xffffffffu, su1, 2);
        l0 = l0 * sc0 + su0;
        l1 = l1 * sc1 + su1;
#pragma unroll
        for (int j = 0; j < 8; j++) {
            o[j][0] *= sc0;
            o[j][1] *= sc0;
            o[j][2] *= sc1;
            o[j][3] *= sc1;
        }

        // O += P @ V (split-bf16: PhVh + PlVh + PhVl)
#pragma unroll
        for (int kf = 0; kf < 4; kf++) {
            uint32_t ph[4], pl[4];
            split2(s[2 * kf][0], s[2 * kf][1], ph[0], pl[0]);
            split2(s[2 * kf][2], s[2 * kf][3], ph[1], pl[1]);
            split2(s[2 * kf + 1][0], s[2 * kf + 1][1], ph[2], pl[2]);
            split2(s[2 * kf + 1][2], s[2 * kf + 1][3], ph[3], pl[3]);
            uint32_t vh[4][4], vl[4][4];
#pragma unroll
            for (int nb = 0; nb < 4; nb++) {
                uint32_t boff = (uint32_t)(kf * 16 + lr) * R + (uint32_t)(nb * 16 + ac8) * 2;
                ldsm4t(vh[nb], sb + VHS + boff);
            }
#pragma unroll
            for (int nb = 0; nb < 4; nb++) {
                mma_bf16(o[2 * nb], ph, &vh[nb][0]);
                mma_bf16(o[2 * nb + 1], ph, &vh[nb][2]);
                mma_bf16(o[2 * nb], pl, &vh[nb][0]);
                mma_bf16(o[2 * nb + 1], pl, &vh[nb][2]);
            }
#pragma unroll
            for (int nb = 0; nb < 4; nb++) {
                uint32_t boff = (uint32_t)(kf * 16 + lr) * R + (uint32_t)(nb * 16 + ac8) * 2;
                ldsm4t(vl[nb], sb + VLS + boff);
            }
#pragma unroll
            for (int nb = 0; nb < 4; nb++) {
                mma_bf16(o[2 * nb], ph, &vl[nb][0]);
                mma_bf16(o[2 * nb + 1], ph, &vl[nb][2]);
            }
        }
        __syncthreads();
    }

    // epilogue
    float i0 = 1.f / l0, i1 = 1.f / l1;
    const int g = lane >> 2, q = lane & 3;
    float* Ob = O + (size_t)(qb * 128 + wid * 16) * DD + h * HD;
#pragma unroll
    for (int nj = 0; nj < 8; nj++) {
        int col = nj * 8 + q * 2;
        *(float2*)(Ob + (size_t)g * DD + col) = make_float2(o[nj][0] * i0, o[nj][1] * i0);
        *(float2*)(Ob + (size_t)(g + 8) * DD + col) =
            make_float2(o[nj][2] * i1, o[nj][3] * i1);
    }
}

// ---------------- launch -----------------------------------------------------
extern "C" void kernel_launch(void* const* d_in, const int* in_sizes, int n_in,
                              void* d_out, int out_size) {
    const float* x     = (const float*)d_in[0];
    const float* ctx   = (const float*)d_in[1];
    const float* wq    = (const float*)d_in[2];
    const float* bq    = (const float*)d_in[3];
    const float* wk    = (const float*)d_in[4];
    const float* bk    = (const float*)d_in[5];
    const float* wv    = (const float*)d_in[6];
    const float* bv    = (const float*)d_in[7];
    const float* wo    = (const float*)d_in[8];
    const float* bo    = (const float*)d_in[9];
    const float* w1    = (const float*)d_in[10];
    const float* b1    = (const float*)d_in[11];
    const float* w2    = (const float*)d_in[12];
    const float* b2    = (const float*)d_in[13];
    const float* qn_w  = (const float*)d_in[14];
    const float* qn_b  = (const float*)d_in[15];
    const float* kvn_w = (const float*)d_in[16];
    const float* kvn_b = (const float*)d_in[17];
    const float* pn_w  = (const float*)d_in[18];
    const float* pn_b  = (const float*)d_in[19];
    float* out = (float*)d_out;

    float *xq, *kv, *q, *k, *v, *o, *x1, *hln, *h1;
    cudaGetSymbolAddress((void**)&xq, g_xq);
    cudaGetSymbolAddress((void**)&kv, g_kv);
    cudaGetSymbolAddress((void**)&q, g_q);
    cudaGetSymbolAddress((void**)&k, g_k);
    cudaGetSymbolAddress((void**)&v, g_v);
    cudaGetSymbolAddress((void**)&o, g_o);
    cudaGetSymbolAddress((void**)&x1, g_x1);
    cudaGetSymbolAddress((void**)&hln, g_hln);
    cudaGetSymbolAddress((void**)&h1, g_h1);

    const int GSM = 2 * 37888;   // tc_gemm dynamic smem (75776)
    const int FSM = 73728;       // flash dynamic smem
    cudaFuncSetAttribute((const void*)tc_gemm<1, 0, 0>,
                         cudaFuncAttributeMaxDynamicSharedMemorySize, GSM);
    cudaFuncSetAttribute((const void*)tc_gemm<1, 1, 0>,
                         cudaFuncAttributeMaxDynamicSharedMemorySize, GSM);
    cudaFuncSetAttribute((const void*)tc_gemm<1, 0, 1>,
                         cudaFuncAttributeMaxDynamicSharedMemorySize, GSM);
    cudaFuncSetAttribute((const void*)flash_kernel,
                         cudaFuncAttributeMaxDynamicSharedMemorySize, FSM);

    // 1. pre-norms
    layernorm_kernel<DD><<<NT, 256>>>(x, qn_w, qn_b, xq);
    layernorm_kernel<CC><<<MT, 256>>>(ctx, kvn_w, kvn_b, kv);

    // 2. Q/K/V projections
    tc_gemm<1, 0, 0><<<dim3(DD / 128, NT / 128), 256, GSM>>>(xq, wq, bq, nullptr, q, DD, DD);
    tc_gemm<1, 0, 0><<<dim3(DD / 128, MT / 128), 256, GSM>>>(kv, wk, bk, nullptr, k, CC, DD);
    tc_gemm<1, 0, 0><<<dim3(DD / 128, MT / 128), 256, GSM>>>(kv, wv, bv, nullptr, v, CC, DD);

    // 3. fused attention
    flash_kernel<<<dim3(NT / 128, NH), 256, FSM>>>(q, k, v, o);

    // 4. x1 = o @ wo + bo + x
    tc_gemm<1, 1, 0><<<dim3(DD / 128, NT / 128), 256, GSM>>>(o, wo, bo, x, x1, DD, DD);

    // 5. MLP
    layernorm_kernel<DD><<<NT, 256>>>(x1, pn_w, pn_b, hln);
    tc_gemm<1, 0, 1><<<dim3(FF / 128, NT / 128), 256, GSM>>>(hln, w1, b1, nullptr, h1, DD, FF);
    tc_gemm<1, 1, 0><<<dim3(DD / 128, NT / 128), 256, GSM>>>(h1, w2, b2, x1, out, FF, DD);
}

// round 5
// speedup vs baseline: 2.9370x; 1.8285x over previous
#include <cuda_runtime.h>
#include <cuda_bf16.h>
#include <math.h>
#include <stdint.h>

#define NT 2048
#define DD 1024
#define CC 768
#define NH 16
#define HD 64
#define MT 2048
#define FF 4096

typedef unsigned short ushortx;

// ---------------- scratch (bf16 pairs stored as ushort) ----------------------
__device__ ushortx g_xqh[NT * DD], g_xql[NT * DD];
__device__ ushortx g_kvh[MT * CC], g_kvl[MT * CC];
__device__ ushortx g_qh[NT * DD], g_ql[NT * DD];
__device__ ushortx g_kh[MT * DD], g_kl[MT * DD];
__device__ ushortx g_vh[MT * DD], g_vl[MT * DD];
__device__ ushortx g_oh[NT * DD], g_ol[NT * DD];
__device__ float   g_x1[NT * DD];
__device__ ushortx g_hlnh[NT * DD], g_hlnl[NT * DD];
__device__ ushortx g_h1h[(size_t)NT * FF], g_h1l[(size_t)NT * FF];
__device__ ushortx g_wqh[DD * DD], g_wql[DD * DD];
__device__ ushortx g_wkh[CC * DD], g_wkl[CC * DD];
__device__ ushortx g_wvh[CC * DD], g_wvl[CC * DD];
__device__ ushortx g_woh[DD * DD], g_wol[DD * DD];
__device__ ushortx g_w1h[(size_t)DD * FF], g_w1l[(size_t)DD * FF];
__device__ ushortx g_w2h[(size_t)FF * DD], g_w2l[(size_t)FF * DD];

// ---------------- helpers ----------------------------------------------------
__device__ __forceinline__ uint32_t smem_addr_u32(const void* p) {
    uint32_t a;
    asm("{ .reg .u64 t; cvta.to.shared.u64 t, %1; cvt.u32.u64 %0, t; }" : "=r"(a) : "l"(p));
    return a;
}
__device__ __forceinline__ void ldsm4(uint32_t* r, uint32_t addr) {
    asm volatile("ldmatrix.sync.aligned.m8n8.x4.shared.b16 {%0,%1,%2,%3}, [%4];"
                 : "=r"(r[0]), "=r"(r[1]), "=r"(r[2]), "=r"(r[3]) : "r"(addr));
}
__device__ __forceinline__ void ldsm4t(uint32_t* r, uint32_t addr) {
    asm volatile("ldmatrix.sync.aligned.m8n8.x4.trans.shared.b16 {%0,%1,%2,%3}, [%4];"
                 : "=r"(r[0]), "=r"(r[1]), "=r"(r[2]), "=r"(r[3]) : "r"(addr));
}
__device__ __forceinline__ void mma_bf16(float* d, const uint32_t* a, const uint32_t* b) {
    asm volatile(
        "mma.sync.aligned.m16n8k16.row.col.f32.bf16.bf16.f32 "
        "{%0,%1,%2,%3}, {%4,%5,%6,%7}, {%8,%9}, {%0,%1,%2,%3};"
        : "+f"(d[0]), "+f"(d[1]), "+f"(d[2]), "+f"(d[3])
        : "r"(a[0]), "r"(a[1]), "r"(a[2]), "r"(a[3]), "r"(b[0]), "r"(b[1]));
}
__device__ __forceinline__ void split2(float x, float y, uint32_t& h, uint32_t& l) {
    __nv_bfloat16 xh = __float2bfloat16(x), yh = __float2bfloat16(y);
    float xr = x - __bfloat162float(xh);
    float yr = y - __bfloat162float(yh);
    __nv_bfloat16 xl = __float2bfloat16(xr), yl = __float2bfloat16(yr);
    h = (uint32_t)__bfloat16_as_ushort(xh) | ((uint32_t)__bfloat16_as_ushort(yh) << 16);
    l = (uint32_t)__bfloat16_as_ushort(xl) | ((uint32_t)__bfloat16_as_ushort(yl) << 16);
}
__device__ __forceinline__ void cpa16(uint32_t d, const void* g) {
    asm volatile("cp.async.cg.shared.global [%0], [%1], 16;" :: "r"(d), "l"(g));
}
__device__ __forceinline__ void cpcommit() { asm volatile("cp.async.commit_group;" ::: "memory"); }
template <int N>
__device__ __forceinline__ void cpwait() {
    asm volatile("cp.async.wait_group %0;" :: "n"(N) : "memory");
}

// ---------------- convert fp32 -> bf16 hi/lo ---------------------------------
__global__ __launch_bounds__(256) void convert_kernel(
    const float* __restrict__ s, ushortx* __restrict__ h, ushortx* __restrict__ l, int n4) {
    int i = blockIdx.x * 256 + threadIdx.x;
    if (i >= n4) return;
    float4 f = ((const float4*)s)[i];
    uint32_t h0, l0, h1, l1;
    split2(f.x, f.y, h0, l0);
    split2(f.z, f.w, h1, l1);
    ((uint2*)h)[i] = make_uint2(h0, h1);
    ((uint2*)l)[i] = make_uint2(l0, l1);
}

// ---------------- layernorm -> bf16 pair -------------------------------------
__device__ __forceinline__ float block_reduce_sum(float v) {
    __shared__ float sh[8];
    int tid = threadIdx.x;
#pragma unroll
    for (int o = 16; o > 0; o >>= 1) v += __shfl_down_sync(0xffffffffu, v, o);
    if ((tid & 31) == 0) sh[tid >> 5] = v;
    __syncthreads();
    if (tid < 32) {
        v = (tid < 8) ? sh[tid] : 0.f;
#pragma unroll
        for (int o = 4; o > 0; o >>= 1) v += __shfl_down_sync(0xffffffffu, v, o);
        if (tid == 0) sh[0] = v;
    }
    __syncthreads();
    float r = sh[0];
    __syncthreads();
    return r;
}

template <int DIM>
__global__ __launch_bounds__(256) void ln_pair_kernel(
    const float* __restrict__ x, const float* __restrict__ w, const float* __restrict__ b,
    ushortx* __restrict__ oh, ushortx* __restrict__ ol) {
    const float* xr = x + (size_t)blockIdx.x * DIM;
    int tid = threadIdx.x;
    float4 f = make_float4(0.f, 0.f, 0.f, 0.f);
    if (tid < DIM / 4) f = ((const float4*)xr)[tid];
    float s = f.x + f.y + f.z + f.w;
    float mean = block_reduce_sum(s) * (1.f / DIM);
    float vv = 0.f;
    if (tid < DIM / 4) {
        float c0 = f.x - mean, c1 = f.y - mean, c2 = f.z - mean, c3 = f.w - mean;
        vv = c0 * c0 + c1 * c1 + c2 * c2 + c3 * c3;
    }
    float var = block_reduce_sum(vv) * (1.f / DIM);
    float inv = rsqrtf(var + 1e-12f);
    if (tid < DIM / 4) {
        float4 w4 = ((const float4*)w)[tid];
        float4 b4 = ((const float4*)b)[tid];
        float o0 = (f.x - mean) * inv * w4.x + b4.x;
        float o1 = (f.y - mean) * inv * w4.y + b4.y;
        float o2 = (f.z - mean) * inv * w4.z + b4.z;
        float o3 = (f.w - mean) * inv * w4.w + b4.w;
        uint32_t h0, l0, h1, l1;
        split2(o0, o1, h0, l0);
        split2(o2, o3, h1, l1);
        ((uint2*)(oh + (size_t)blockIdx.x * DIM))[tid] = make_uint2(h0, h1);
        ((uint2*)(ol + (size_t)blockIdx.x * DIM))[tid] = make_uint2(l0, l1);
    }
}

// ---------------- bf16-pair GEMM core -----------------------------------------
// C[128x128] tile at (bx,by): A pair [M,K] lda=K; B pair [K,N] ldb.
// RES: add fp32 Res. GELU. OUTPAIR: write bf16 pair, else fp32.
template <int RES, int GELU, int OUTPAIR>
__device__ __forceinline__ void gemm_core(
    const ushortx* __restrict__ Ah, const ushortx* __restrict__ Al,
    const ushortx* __restrict__ Bh, const ushortx* __restrict__ Bl,
    const float* __restrict__ bias, const float* __restrict__ Res,
    float* __restrict__ Cf, ushortx* __restrict__ Ch, ushortx* __restrict__ Cl,
    int K, int lda, int ldb, int bx, int by) {
    constexpr int RA = 80, RB = 272;
    constexpr int ASZ = 128 * RA;      // 10240
    constexpr int BSZ = 32 * RB;       // 8704
    constexpr int STAGE = 2 * ASZ + 2 * BSZ;  // 37888

    extern __shared__ char sm[];
    const int tid = threadIdx.x, lane = tid & 31, wid = tid >> 5;
    const int wm = wid & 1, wn = wid >> 1;
    const uint32_t sb = smem_addr_u32(sm);

    const ushortx* Abh = Ah + (size_t)by * 128 * lda;
    const ushortx* Abl = Al + (size_t)by * 128 * lda;
    const ushortx* Bbh = Bh + (size_t)bx * 128;
    const ushortx* Bbl = Bl + (size_t)bx * 128;

    auto issue = [&](int k0, int buf) {
        uint32_t d = sb + buf * STAGE;
#pragma unroll
        for (int j = 0; j < 2; j++) {
            int i = tid + j * 256;
            int r = i >> 2, s = i & 3;
            uint32_t dd = d + (uint32_t)(r * RA + s * 16);
            size_t so = (size_t)r * lda + k0 + s * 8;
            cpa16(dd, Abh + so);
            cpa16(dd + ASZ, Abl + so);
        }
#pragma unroll
        for (int j = 0; j < 2; j++) {
            int i = tid + j * 256;
            int kr = i >> 4, s = i & 15;
            uint32_t dd = d + 2 * ASZ + (uint32_t)(kr * RB + s * 16);
            size_t so = (size_t)(k0 + kr) * ldb + s * 8;
            cpa16(dd, Bbh + so);
            cpa16(dd + BSZ, Bbl + so);
        }
        cpcommit();
    };

    float acc[4][4][4];
#pragma unroll
    for (int i = 0; i < 4; i++)
#pragma unroll
        for (int j = 0; j < 4; j++)
#pragma unroll
            for (int q = 0; q < 4; q++) acc[i][j][q] = 0.f;

    const int lr = lane & 15;
    const int ac8 = (lane >> 4) << 3;

    auto domma = [&](int buf) {
        const uint32_t ah = sb + buf * STAGE;
        const uint32_t al = ah + ASZ;
        const uint32_t bh = al + ASZ;
        const uint32_t bl = bh + BSZ;
#pragma unroll
        for (int kk = 0; kk < 2; kk++) {
            uint32_t bhf[2][4], blf[2][4];
#pragma unroll
            for (int nb = 0; nb < 2; nb++) {
                uint32_t boff = (uint32_t)(kk * 16 + lr) * RB +
                                (uint32_t)(wn * 32 + nb * 16 + ac8) * 2;
                ldsm4t(bhf[nb], bh + boff);
                ldsm4t(blf[nb], bl + boff);
            }
#pragma unroll
            for (int mi = 0; mi < 4; mi++) {
                uint32_t aoff = (uint32_t)(wm * 64 + mi * 16 + lr) * RA +
                                (uint32_t)(kk * 16 + ac8) * 2;
                uint32_t ahf[4], alf[4];
                ldsm4(ahf, ah + aoff);
#pragma unroll
                for (int nb = 0; nb < 2; nb++) {
                    mma_bf16(acc[mi][2 * nb], ahf, &bhf[nb][0]);
                    mma_bf16(acc[mi][2 * nb + 1], ahf, &bhf[nb][2]);
                    mma_bf16(acc[mi][2 * nb], ahf, &blf[nb][0]);
                    mma_bf16(acc[mi][2 * nb + 1], ahf, &blf[nb][2]);
                }
                ldsm4(alf, al + aoff);
#pragma unroll
                for (int nb = 0; nb < 2; nb++) {
                    mma_bf16(acc[mi][2 * nb], alf, &bhf[nb][0]);
                    mma_bf16(acc[mi][2 * nb + 1], alf, &bhf[nb][2]);
                }
            }
        }
    };

    const int T = K >> 5;
    issue(0, 0);
    issue(32, 1);
    cpwait<1>();
    __syncthreads();
#pragma unroll 1
    for (int t = 0; t < T; t++) {
        domma(t & 1);
        __syncthreads();
        if (t + 2 < T) issue((t + 2) * 32, t & 1);
        if (t + 1 < T) {
            if (t + 2 < T) cpwait<1>();
            else cpwait<0>();
            __syncthreads();
        }
    }

    // epilogue
    const int g = lane >> 2, q = lane & 3;
    const size_t c0 = (size_t)by * 128 * ldb + (size_t)bx * 128;
#pragma unroll
    for (int mi = 0; mi < 4; mi++)
#pragma unroll
        for (int nj = 0; nj < 4; nj++) {
            int col = wn * 32 + nj * 8 + q * 2;
            float bv0 = bias[bx * 128 + col], bv1 = bias[bx * 128 + col + 1];
#pragma unroll
            for (int rr = 0; rr < 2; rr++) {
                int row = wm * 64 + mi * 16 + g + rr * 8;
                float v0 = acc[mi][nj][rr * 2] + bv0;
                float v1 = acc[mi][nj][rr * 2 + 1] + bv1;
                if (RES) {
                    const float* rp = Res + c0 + (size_t)row * ldb + col;
                    v0 += rp[0];
                    v1 += rp[1];
                }
                if (GELU) {
                    float i0 = 0.7978845608028654f * (v0 + 0.044715f * v0 * v0 * v0);
                    v0 = 0.5f * v0 * (1.f + tanhf(i0));
                    float i1 = 0.7978845608028654f * (v1 + 0.044715f * v1 * v1 * v1);
                    v1 = 0.5f * v1 * (1.f + tanhf(i1));
                }
                if (OUTPAIR) {
                    uint32_t hw, lw;
                    split2(v0, v1, hw, lw);
                    *(uint32_t*)(Ch + c0 + (size_t)row * ldb + col) = hw;
                    *(uint32_t*)(Cl + c0 + (size_t)row * ldb + col) = lw;
                } else {
                    *(float2*)(Cf + c0 + (size_t)row * ldb + col) = make_float2(v0, v1);
                }
            }
        }
}

template <int RES, int GELU, int OUTPAIR>
__global__ __launch_bounds__(256, 2) void pair_gemm(
    const ushortx* Ah, const ushortx* Al, const ushortx* Bh, const ushortx* Bl,
    const float* bias, const float* Res, float* Cf, ushortx* Ch, ushortx* Cl,
    int K, int lda, int ldb) {
    gemm_core<RES, GELU, OUTPAIR>(Ah, Al, Bh, Bl, bias, Res, Cf, Ch, Cl, K, lda, ldb,
                                  blockIdx.x, blockIdx.y);
}

// fused QKV: z=0 -> q = xq@wq+bq ; z=1 -> k = kv@wk+bk ; z=2 -> v = kv@wv+bv
__global__ __launch_bounds__(256, 2) void qkv_gemm(
    const ushortx* xqh, const ushortx* xql, const ushortx* kvh, const ushortx* kvl,
    const ushortx* wqh, const ushortx* wql, const ushortx* wkh, const ushortx* wkl,
    const ushortx* wvh, const ushortx* wvl,
    const float* bq, const float* bk, const float* bv,
    ushortx* qh, ushortx* ql, ushortx* kh, ushortx* kl, ushortx* vh, ushortx* vl) {
    int z = blockIdx.z;
    const ushortx *Ah, *Al, *Bh, *Bl;
    const float* bias;
    ushortx *Ch, *Cl;
    int K, lda;
    if (z == 0) {
        Ah = xqh; Al = xql; Bh = wqh; Bl = wql; bias = bq; Ch = qh; Cl = ql;
        K = DD; lda = DD;
    } else if (z == 1) {
        Ah = kvh; Al = kvl; Bh = wkh; Bl = wkl; bias = bk; Ch = kh; Cl = kl;
        K = CC; lda = CC;
    } else {
        Ah = kvh; Al = kvl; Bh = wvh; Bl = wvl; bias = bv; Ch = vh; Cl = vl;
        K = CC; lda = CC;
    }
    gemm_core<0, 0, 1>(Ah, Al, Bh, Bl, bias, nullptr, nullptr, Ch, Cl, K, lda, DD,
                       blockIdx.x, blockIdx.y);
}

// ---------------- flash attention (bf16-pair in/out) --------------------------
__global__ __launch_bounds__(256, 2) void flash_kernel(
    const ushortx* __restrict__ Qh, const ushortx* __restrict__ Ql,
    const ushortx* __restrict__ Kh, const ushortx* __restrict__ Kl,
    const ushortx* __restrict__ Vh, const ushortx* __restrict__ Vl,
    ushortx* __restrict__ Oh, ushortx* __restrict__ Ol) {
    constexpr int R = 144;
    constexpr int QHo = 0, QLo = 18432, KHS = 36864, KLS = 46080, VHS = 55296, VLS = 64512;

    extern __shared__ char sm[];
    const int tid = threadIdx.x, lane = tid & 31, wid = tid >> 5;
    const int h = blockIdx.y, qb = blockIdx.x;
    const uint32_t sb = smem_addr_u32(sm);

    const ushortx* Qgh = Qh + (size_t)qb * 128 * DD + h * HD;
    const ushortx* Qgl = Ql + (size_t)qb * 128 * DD + h * HD;
    const ushortx* Kgh = Kh + h * HD;
    const ushortx* Kgl = Kl + h * HD;
    const ushortx* Vgh = Vh + h * HD;
    const ushortx* Vgl = Vl + h * HD;

    // issue Q (128x64 hi/lo)
#pragma unroll
    for (int j = 0; j < 4; j++) {
        int i = tid + j * 256;
        int r = i >> 3, s = i & 7;
        uint32_t dd = sb + (uint32_t)(r * R + s * 16);
        size_t so = (size_t)r * DD + s * 8;
        cpa16(dd + QHo, Qgh + so);
        cpa16(dd + QLo, Qgl + so);
    }
    auto issueKV = [&](int kb) {
#pragma unroll
        for (int j = 0; j < 2; j++) {
            int i = tid + j * 256;
            int r = i >> 3, s = i & 7;
            uint32_t dd = sb + (uint32_t)(r * R + s * 16);
            size_t so = (size_t)(kb * 64 + r) * DD + s * 8;
            cpa16(dd + KHS, Kgh + so);
            cpa16(dd + KLS, Kgl + so);
            cpa16(dd + VHS, Vgh + so);
            cpa16(dd + VLS, Vgl + so);
        }
        cpcommit();
    };
    issueKV(0);

    float o[8][4];
#pragma unroll
    for (int i = 0; i < 8; i++)
#pragma unroll
        for (int j = 0; j < 4; j++) o[i][j] = 0.f;
    float m0 = -INFINITY, m1 = -INFINITY, l0 = 0.f, l1 = 0.f;

    const int lr = lane & 15;
    const int ac8 = (lane >> 4) << 3;
    const int bn = (lane & 7) + ((lane >> 4) << 3);
    const int bc8 = ((lane >> 3) & 1) << 3;

    for (int kb = 0; kb < MT / 64; kb++) {
        cpwait<0>();
        __syncthreads();

        // S = Q @ K^T (3 split products)
        float s[8][4];
#pragma unroll
        for (int i = 0; i < 8; i++)
#pragma unroll
            for (int j = 0; j < 4; j++) s[i][j] = 0.f;
#pragma unroll
        for (int kf = 0; kf < 4; kf++) {
            uint32_t aoff = (uint32_t)(wid * 16 + lr) * R + (uint32_t)(kf * 16 + ac8) * 2;
            uint32_t qhr[4], qlr[4], khr[4][4], klr[4][4];
            ldsm4(qhr, sb + QHo + aoff);
#pragma unroll
            for (int nb = 0; nb < 4; nb++) {
                uint32_t boff = (uint32_t)(nb * 16 + bn) * R + (uint32_t)(kf * 16 + bc8) * 2;
                ldsm4(khr[nb], sb + KHS + boff);
            }
#pragma unroll
            for (int nb = 0; nb < 4; nb++) {
                mma_bf16(s[2 * nb], qhr, &khr[nb][0]);
                mma_bf16(s[2 * nb + 1], qhr, &khr[nb][2]);
            }
            ldsm4(qlr, sb + QLo + aoff);
#pragma unroll
            for (int nb = 0; nb < 4; nb++) {
                mma_bf16(s[2 * nb], qlr, &khr[nb][0]);
                mma_bf16(s[2 * nb + 1], qlr, &khr[nb][2]);
            }
#pragma unroll
            for (int nb = 0; nb < 4; nb++) {
                uint32_t boff = (uint32_t)(nb * 16 + bn) * R + (uint32_t)(kf * 16 + bc8) * 2;
                ldsm4(klr[nb], sb + KLS + boff);
            }
#pragma unroll
            for (int nb = 0; nb < 4; nb++) {
                mma_bf16(s[2 * nb], qhr, &klr[nb][0]);
                mma_bf16(s[2 * nb + 1], qhr, &klr[nb][2]);
            }
        }

        // online softmax
        float mx0 = -INFINITY, mx1 = -INFINITY;
#pragma unroll
        for (int j = 0; j < 8; j++) {
            mx0 = fmaxf(mx0, fmaxf(s[j][0], s[j][1]));
            mx1 = fmaxf(mx1, fmaxf(s[j][2], s[j][3]));
        }
        mx0 = fmaxf(mx0, __shfl_xor_sync(0xffffffffu, mx0, 1));
        mx0 = fmaxf(mx0, __shfl_xor_sync(0xffffffffu, mx0, 2));
        mx1 = fmaxf(mx1, __shfl_xor_sync(0xffffffffu, mx1, 1));
        mx1 = fmaxf(mx1, __shfl_xor_sync(0xffffffffu, mx1, 2));
        float m0n = fmaxf(m0, mx0), m1n = fmaxf(m1, mx1);
        float sc0 = __expf((m0 - m0n) * 0.125f);
        float sc1 = __expf((m1 - m1n) * 0.125f);
        m0 = m0n;
        m1 = m1n;
        float su0 = 0.f, su1 = 0.f;
#pragma unroll
        for (int j = 0; j < 8; j++) {
            s[j][0] = __expf((s[j][0] - m0) * 0.125f);
            s[j][1] = __expf((s[j][1] - m0) * 0.125f);
            s[j][2] = __expf((s[j][2] - m1) * 0.125f);
            s[j][3] = __expf((s[j][3] - m1) * 0.125f);
            su0 += s[j][0] + s[j][1];
            su1 += s[j][2] + s[j][3];
        }
        su0 += __shfl_xor_sync(0xffffffffu, su0, 1);
        su0 += __shfl_xor_sync(0xffffffffu, su0, 2);
        su1 += __shfl_xor_sync(0xffffffffu, su1, 1);
        su1 += __shfl_xor_sync(0xffffffffu, su1, 2);
        l0 = l0 * sc0 + su0;
        l1 = l1 * sc1 + su1;
#pragma unroll
        for (int j = 0; j < 8; j++) {
            o[j][0] *= sc0;
            o[j][1] *= sc0;
            o[j][2] *= sc1;
            o[j][3] *= sc1;
        }

        // O += P @ V (split: PhVh + PlVh + PhVl)
#pragma unroll
        for (int kf = 0; kf < 4; kf++) {
            uint32_t ph[4], pl[4];
            split2(s[2 * kf][0], s[2 * kf][1], ph[0], pl[0]);
            split2(s[2 * kf][2], s[2 * kf][3], ph[1], pl[1]);
            split2(s[2 * kf + 1][0], s[2 * kf + 1][1], ph[2], pl[2]);
            split2(s[2 * kf + 1][2], s[2 * kf + 1][3], ph[3], pl[3]);
            uint32_t vhr[4][4], vlr[4][4];
#pragma unroll
            for (int nb = 0; nb < 4; nb++) {
                uint32_t boff = (uint32_t)(kf * 16 + lr) * R + (uint32_t)(nb * 16 + ac8) * 2;
                ldsm4t(vhr[nb], sb + VHS + boff);
            }
#pragma unroll
            for (int nb = 0; nb < 4; nb++) {
                mma_bf16(o[2 * nb], ph, &vhr[nb][0]);
                mma_bf16(o[2 * nb + 1], ph, &vhr[nb][2]);
                mma_bf16(o[2 * nb], pl, &vhr[nb][0]);
                mma_bf16(o[2 * nb + 1], pl, &vhr[nb][2]);
            }
#pragma unroll
            for (int nb = 0; nb < 4; nb++) {
                uint32_t boff = (uint32_t)(kf * 16 + lr) * R + (uint32_t)(nb * 16 + ac8) * 2;
                ldsm4t(vlr[nb], sb + VLS + boff);
            }
#pragma unroll
            for (int nb = 0; nb < 4; nb++) {
                mma_bf16(o[2 * nb], ph, &vlr[nb][0]);
                mma_bf16(o[2 * nb + 1], ph, &vlr[nb][2]);
            }
        }
        __syncthreads();
        if (kb + 1 < MT / 64) issueKV(kb + 1);
    }

    // epilogue: write bf16 pair
    float i0 = 1.f / l0, i1 = 1.f / l1;
    const int g = lane >> 2, q = lane & 3;
    size_t base = (size_t)(qb * 128 + wid * 16) * DD + h * HD;
#pragma unroll
    for (int nj = 0; nj < 8; nj++) {
        int col = nj * 8 + q * 2;
        uint32_t hw, lw;
        split2(o[nj][0] * i0, o[nj][1] * i0, hw, lw);
        *(uint32_t*)(Oh + base + (size_t)g * DD + col) = hw;
        *(uint32_t*)(Ol + base + (size_t)g * DD + col) = lw;
        split2(o[nj][2] * i1, o[nj][3] * i1, hw, lw);
        *(uint32_t*)(Oh + base + (size_t)(g + 8) * DD + col) = hw;
        *(uint32_t*)(Ol + base + (size_t)(g + 8) * DD + col) = lw;
    }
}

// ---------------- launch -----------------------------------------------------
extern "C" void kernel_launch(void* const* d_in, const int* in_sizes, int n_in,
                              void* d_out, int out_size) {
    const float* x     = (const float*)d_in[0];
    const float* ctx   = (const float*)d_in[1];
    const float* wq    = (const float*)d_in[2];
    const float* bq    = (const float*)d_in[3];
    const float* wk    = (const float*)d_in[4];
    const float* bk    = (const float*)d_in[5];
    const float* wv    = (const float*)d_in[6];
    const float* bv    = (const float*)d_in[7];
    const float* wo    = (const float*)d_in[8];
    const float* bo    = (const float*)d_in[9];
    const float* w1    = (const float*)d_in[10];
    const float* b1    = (const float*)d_in[11];
    const float* w2    = (const float*)d_in[12];
    const float* b2    = (const float*)d_in[13];
    const float* qn_w  = (const float*)d_in[14];
    const float* qn_b  = (const float*)d_in[15];
    const float* kvn_w = (const float*)d_in[16];
    const float* kvn_b = (const float*)d_in[17];
    const float* pn_w  = (const float*)d_in[18];
    const float* pn_b  = (const float*)d_in[19];
    float* out = (float*)d_out;

#define GETP(name) \
    ushortx* name; cudaGetSymbolAddress((void**)&name, g_##name)
    GETP(xqh); GETP(xql); GETP(kvh); GETP(kvl);
    GETP(qh); GETP(ql); GETP(kh); GETP(kl); GETP(vh); GETP(vl);
    GETP(oh); GETP(ol); GETP(hlnh); GETP(hlnl); GETP(h1h); GETP(h1l);
    GETP(wqh); GETP(wql); GETP(wkh); GETP(wkl); GETP(wvh); GETP(wvl);
    GETP(woh); GETP(wol); GETP(w1h); GETP(w1l); GETP(w2h); GETP(w2l);
#undef GETP
    float* x1;
    cudaGetSymbolAddress((void**)&x1, g_x1);

    const int GSM = 2 * 37888;   // 75776
    const int FSM = 73728;
    cudaFuncSetAttribute((const void*)qkv_gemm,
                         cudaFuncAttributeMaxDynamicSharedMemorySize, GSM);
    cudaFuncSetAttribute((const void*)pair_gemm<1, 0, 0>,
                         cudaFuncAttributeMaxDynamicSharedMemorySize, GSM);
    cudaFuncSetAttribute((const void*)pair_gemm<0, 1, 1>,
                         cudaFuncAttributeMaxDynamicSharedMemorySize, GSM);
    cudaFuncSetAttribute((const void*)flash_kernel,
                         cudaFuncAttributeMaxDynamicSharedMemorySize, FSM);

    // 0. convert weights to bf16 pairs
    convert_kernel<<<(DD * DD / 4 + 255) / 256, 256>>>(wq, wqh, wql, DD * DD / 4);
    convert_kernel<<<(CC * DD / 4 + 255) / 256, 256>>>(wk, wkh, wkl, CC * DD / 4);
    convert_kernel<<<(CC * DD / 4 + 255) / 256, 256>>>(wv, wvh, wvl, CC * DD / 4);
    convert_kernel<<<(DD * DD / 4 + 255) / 256, 256>>>(wo, woh, wol, DD * DD / 4);
    convert_kernel<<<(DD * FF / 4 + 255) / 256, 256>>>(w1, w1h, w1l, DD * FF / 4);
    convert_kernel<<<(FF * DD / 4 + 255) / 256, 256>>>(w2, w2h, w2l, FF * DD / 4);

    // 1. pre-norms -> bf16 pairs
    ln_pair_kernel<DD><<<NT, 256>>>(x, qn_w, qn_b, xqh, xql);
    ln_pair_kernel<CC><<<MT, 256>>>(ctx, kvn_w, kvn_b, kvh, kvl);

    // 2. fused Q/K/V projections
    qkv_gemm<<<dim3(DD / 128, NT / 128, 3), 256, GSM>>>(
        xqh, xql, kvh, kvl, wqh, wql, wkh, wkl, wvh, wvl, bq, bk, bv,
        qh, ql, kh, kl, vh, vl);

    // 3. fused attention
    flash_kernel<<<dim3(NT / 128, NH), 256, FSM>>>(qh, ql, kh, kl, vh, vl, oh, ol);

    // 4. x1 = o @ wo + bo + x
    pair_gemm<1, 0, 0><<<dim3(DD / 128, NT / 128), 256, GSM>>>(
        oh, ol, woh, wol, bo, x, x1, nullptr, nullptr, DD, DD, DD);

    // 5. MLP
    ln_pair_kernel<DD><<<NT, 256>>>(x1, pn_w, pn_b, hlnh, hlnl);
    pair_gemm<0, 1, 1><<<dim3(FF / 128, NT / 128), 256, GSM>>>(
        hlnh, hlnl, w1h, w1l, b1, nullptr, nullptr, h1h, h1l, DD, DD, FF);
    pair_gemm<1, 0, 0><<<dim3(DD / 128, NT / 128), 256, GSM>>>(
        h1h, h1l, w2h, w2l, b2, x1, out, nullptr, nullptr, FF, FF, DD);
}